// round 15
// baseline (speedup 1.0000x reference)
#include <cuda_runtime.h>
#include <math.h>

#define GRP 64
#define MN  128
#define NNODES (GRP*MN)
#define NRAD 16
#define SPT 8              // radials per thread
#define SCHUNKS (NRAD/SPT) // 2
#define RSPLIT 4           // receiver quarters per (group, chunk)
#define RPB (MN/RSPLIT)    // 32 receivers per block
#define NSL 8              // j-slices (residue classes mod 8)

struct RadConsts {
    float phw[NRAD];         // 0.3275911 * halfinvw (erf poly d-coef)
    float negl2e_hw2[NRAD];  // -log2(e) * halfinvw^2 (exp from r2)
    float ginv[NRAD];
    float inv2w2[NRAD];
    float l0f[NRAD];
    float l1w[NRAD];
    float si0[NRAD];
    float si1[NRAD];
};

__device__ __forceinline__ float rcp_approx(float x) {
    float r; asm("rcp.approx.f32 %0, %1;" : "=f"(r) : "f"(x)); return r;
}
__device__ __forceinline__ float ex2_approx(float x) {
    float r; asm("ex2.approx.f32 %0, %1;" : "=f"(r) : "f"(x)); return r;
}

__global__ __launch_bounds__(256, 2)
void rsaef_kernel(const float* __restrict__ sf,   // (N,4)
                  const float* __restrict__ pos,  // (N,3)
                  float* __restrict__ out,        // features (N,64) then si (N,64)
                  const RadConsts rc)
{
    // doubled mirrors: index i+q with q in [1,127] needs no wrap mask
    __shared__ float4 sh_pq[2*MN];
    __shared__ float4 sh_mu[2*MN];
    __shared__ float  red[NSL][RPB][SPT*4+1];  // padded stride 33 -> conflict-free

    const int g     = blockIdx.x;
    const int sc    = blockIdx.y;
    const int rbase = blockIdx.z * RPB;
    const int tid   = threadIdx.x;
    const int il    = tid & (RPB - 1);   // receiver within block (0..31)
    const int s     = tid >> 5;          // j-slice (0..7), uniform per warp
    const int i     = rbase + il;        // receiver within group

    if (tid < MN) {
        const float* p = pos + (size_t)g * MN * 3;
        const float* f = sf  + (size_t)g * MN * 4;
        float4 pq;
        pq.x = p[tid*3+0]; pq.y = p[tid*3+1]; pq.z = p[tid*3+2];
        pq.w = f[tid*4+0];
        sh_pq[tid] = pq;  sh_pq[tid + MN] = pq;
        float4 mu;
        mu.x = f[tid*4+3]; mu.y = f[tid*4+1]; mu.z = f[tid*4+2]; mu.w = 0.f;
        sh_mu[tid] = mu;  sh_mu[tid + MN] = mu;
    }
    __syncthreads();

    // radial constants from the param struct (LDC, no FP64)
    float phw[SPT], c2[SPT], ginv[SPT], iw2[SPT];
    #pragma unroll
    for (int t = 0; t < SPT; t++) {
        int k = sc * SPT + t;
        phw[t]  = rc.phw[k];
        c2[t]   = rc.negl2e_hw2[k];
        ginv[t] = rc.ginv[k];
        iw2[t]  = rc.inv2w2[k];
    }

    const float4 me = sh_pq[i];

    float acc0[SPT], a1x[SPT], a1y[SPT], a1z[SPT];
    #pragma unroll
    for (int t = 0; t < SPT; t++) { acc0[t]=0.f; a1x[t]=0.f; a1y[t]=0.f; a1z[t]=0.f; }

    // body: one source j = i + q (never j==i since q in [1,127])
    auto body = [&](int q) {
        const int j = i + q;
        float4 pj  = sh_pq[j];
        float4 muj = sh_mu[j];
        const float qj = pj.w;

        float Rx = me.x - pj.x, Ry = me.y - pj.y, Rz = me.z - pj.z;
        float r2 = fmaf(Rx, Rx, fmaf(Ry, Ry, Rz*Rz));
        float inv_r = rsqrtf(r2);
        float r     = r2 * inv_r;
        float hx = Rx * inv_r, hy = Ry * inv_r, hz = Rz * inv_r;
        float muR = fmaf(muj.x, hx, fmaf(muj.y, hy, muj.z * hz));

        float ir2   = inv_r * inv_r;
        float alpha = muR * inv_r;                   // muR/r
        float gamma = inv_r * fmaf(3.0f, alpha, qj); // qj/r + 3 muR/r^2
        float emx = ir2 * muj.x, emy = ir2 * muj.y, emz = ir2 * muj.z;

        #pragma unroll
        for (int t = 0; t < SPT; t++) {
            float e    = ex2_approx(r2 * c2[t]);     // exp(-u^2)
            float d    = fmaf(phw[t], r, 1.0f);      // erf A&S 7.1.26
            float tt   = rcp_approx(d);
            float P    = fmaf(1.061405429f, tt, -1.453152027f);
            P = fmaf(P, tt, 1.421413741f);
            P = fmaf(P, tt, -0.284496736f);
            P = fmaf(P, tt, 0.254829592f);
            float pe   = (P * tt) * e;
            float T    = fmaf(-pe, inv_r, inv_r);    // erf(u)/r
            float gg   = e * ginv[t];
            float D    = gg - T;

            float A = fmaf(D, gamma, gg * (muR * iw2[t]));

            // l0 contribution is exactly qj*T - alpha*D
            acc0[t] = fmaf(T, qj, acc0[t]);
            acc0[t] = fmaf(-D, alpha, acc0[t]);
            a1x[t]  = fmaf(A, hx, fmaf(-D, emx, a1x[t]));
            a1y[t]  = fmaf(A, hy, fmaf(-D, emy, a1y[t]));
            a1z[t]  = fmaf(A, hz, fmaf(-D, emz, a1z[t]));
        }
    };

    // slice s covers q = 1+s, 9+s, ... ; slices 0..6 do 16 iters, slice 7 does 15
    #pragma unroll 2
    for (int it = 0; it < 15; it++)
        body(1 + s + 8 * it);
    if (s < 7)
        body(121 + s);

    // stash per-slice partials: red[s][il][v], v = t*4 + c (c: 0=l0,1=x,2=y,3=z)
    #pragma unroll
    for (int t = 0; t < SPT; t++) {
        red[s][il][t*4 + 0] = acc0[t];
        red[s][il][t*4 + 1] = a1x[t];
        red[s][il][t*4 + 2] = a1y[t];
        red[s][il][t*4 + 3] = a1z[t];
    }
    __syncthreads();

    // reduce: thread (il, vv) handles radial t=vv, all 4 components
    {
        const int vv   = tid >> 5;          // 0..7 (uniform per warp)
        const int node = g * MN + i;
        const int k    = sc * SPT + vv;
        float* frow = out + (size_t)node * 64;
        float* srow = out + (size_t)NNODES * 64 + (size_t)node * 64;
        const float qi   = sh_pq[i].w;
        const float4 mui = sh_mu[i];        // (sf3, sf1, sf2) = (x,y,z)

        float sum[4];
        #pragma unroll
        for (int c = 0; c < 4; c++) {
            float acc = 0.f;
            #pragma unroll
            for (int ss = 0; ss < NSL; ss++) acc += red[ss][il][vv*4 + c];
            sum[c] = acc;
        }

        frow[k] = rc.l0f[k] * sum[0];
        srow[k] = rc.si0[k] * qi;
        // feature perm: x->+2, y->+0, z->+1 ; si mirrors the same perm
        frow[16 + 3*k + 2] = rc.l1w[k] * sum[1];
        frow[16 + 3*k + 0] = rc.l1w[k] * sum[2];
        frow[16 + 3*k + 1] = rc.l1w[k] * sum[3];
        srow[16 + 3*k + 2] = rc.si1[k] * mui.x;
        srow[16 + 3*k + 0] = rc.si1[k] * mui.y;
        srow[16 + 3*k + 1] = rc.si1[k] * mui.z;
    }
}

static RadConsts make_consts() {
    RadConsts rc;
    const double PI  = 3.14159265358979323846;
    const double KCd = 14.399645351950548;
    const double ISQPI = 0.5641895835477562869480794515607725858;
    const double LOG2E = 1.4426950408889634073599246810018921;
    for (int k = 0; k < NRAD; k++) {
        double sig = 0.5 + (double)k * (2.5 / 15.0);
        double w   = sqrt((1.0 + sig*sig) * 0.5);
        double pi15 = pow(PI, 1.5);
        double s3 = sig*sig*sig;
        double s5 = s3*sig*sig;
        double cl0rec  = 1.0 / sqrt(pi15 * s3);
        double cl0mult = 1.0 / (pow(2.0*PI, 1.5) * s3);
        double cl1rec  = 1.0 / sqrt(pi15 * s5 * 3.0 / 2.0);
        double L0F = cl0rec / cl0mult;
        double L1W = sqrt(3.0) * sig * sig * cl1rec / cl0mult;
        double hw = 0.5 / w;
        rc.phw[k]        = (float)(0.3275911 * hw);
        rc.negl2e_hw2[k] = (float)(-LOG2E * hw * hw);
        rc.ginv[k]       = (float)(ISQPI / w);
        rc.inv2w2[k]     = (float)(1.0 / (2.0 * w * w));
        rc.l0f[k]        = (float)(KCd * L0F);
        rc.l1w[k]        = (float)(KCd * L1W);
        rc.si0[k]        = (float)(KCd * L0F * ISQPI / w);
        rc.si1[k]        = (float)(KCd * L1W / (6.0 * w * w * w) * ISQPI);
    }
    return rc;
}

extern "C" void kernel_launch(void* const* d_in, const int* in_sizes, int n_in,
                              void* d_out, int out_size)
{
    const float* sf  = (const float*)d_in[0];  // source_feats (N,4)
    const float* pos = (const float*)d_in[1];  // node_positions (N,3)
    float* out = (float*)d_out;

    static const RadConsts rc = make_consts();  // host-side, FP64, once

    dim3 grid(GRP, SCHUNKS, RSPLIT);
    rsaef_kernel<<<grid, 256>>>(sf, pos, out, rc);
}

// round 16
// speedup vs baseline: 1.0956x; 1.0956x over previous
#include <cuda_runtime.h>
#include <math.h>

#define GRP 64
#define MN  128
#define NNODES (GRP*MN)
#define NRAD 16
#define SPT 4              // radials per thread
#define SCHUNKS (NRAD/SPT) // 4
#define RSPLIT 4           // receiver quarters per (group, chunk)
#define RPB (MN/RSPLIT)    // 32 receivers per block
#define NSL 8              // j-slices (residue classes mod 8)

struct RadConsts {
    float phw[NRAD];         // 0.3275911 * halfinvw (erf poly d-coef)
    float negl2e_hw2[NRAD];  // -log2(e) * halfinvw^2 (exp from r2)
    float ginv[NRAD];        // 1/(w*sqrt(pi))
    float giw[NRAD];         // ginv * inv2w2  (folds gg*iw2)
    float l0f[NRAD];
    float l1w[NRAD];
    float si0[NRAD];
    float si1[NRAD];
};

__device__ __forceinline__ float rcp_approx(float x) {
    float r; asm("rcp.approx.f32 %0, %1;" : "=f"(r) : "f"(x)); return r;
}
__device__ __forceinline__ float ex2_approx(float x) {
    float r; asm("ex2.approx.f32 %0, %1;" : "=f"(r) : "f"(x)); return r;
}

__global__ __launch_bounds__(256, 4)
void rsaef_kernel(const float* __restrict__ sf,   // (N,4)
                  const float* __restrict__ pos,  // (N,3)
                  float* __restrict__ out,        // features (N,64) then si (N,64)
                  const RadConsts rc)
{
    // doubled mirrors: index i+q with q in [1,127] needs no wrap mask
    __shared__ float4 sh_pq[2*MN];
    __shared__ float4 sh_mu[2*MN];
    __shared__ float  red[NSL][RPB][17];  // padded -> conflict-free

    const int g     = blockIdx.x;
    const int sc    = blockIdx.y;
    const int rbase = blockIdx.z * RPB;
    const int tid   = threadIdx.x;
    const int il    = tid & (RPB - 1);   // receiver within block (0..31)
    const int s     = tid >> 5;          // j-slice (0..7), uniform per warp
    const int i     = rbase + il;        // receiver within group

    if (tid < MN) {
        const float* p = pos + (size_t)g * MN * 3;
        const float* f = sf  + (size_t)g * MN * 4;
        float4 pq;
        pq.x = p[tid*3+0]; pq.y = p[tid*3+1]; pq.z = p[tid*3+2];
        pq.w = f[tid*4+0];
        sh_pq[tid] = pq;  sh_pq[tid + MN] = pq;
        float4 mu;
        mu.x = f[tid*4+3]; mu.y = f[tid*4+1]; mu.z = f[tid*4+2]; mu.w = 0.f;
        sh_mu[tid] = mu;  sh_mu[tid + MN] = mu;
    }
    __syncthreads();

    // radial constants from the param struct (LDC, no FP64)
    float phw[SPT], c2[SPT], ginv[SPT], giw[SPT];
    #pragma unroll
    for (int t = 0; t < SPT; t++) {
        int k = sc * SPT + t;
        phw[t]  = rc.phw[k];
        c2[t]   = rc.negl2e_hw2[k];
        ginv[t] = rc.ginv[k];
        giw[t]  = rc.giw[k];
    }

    const float4 me = sh_pq[i];

    float acc0[SPT], a1x[SPT], a1y[SPT], a1z[SPT];
    #pragma unroll
    for (int t = 0; t < SPT; t++) { acc0[t]=0.f; a1x[t]=0.f; a1y[t]=0.f; a1z[t]=0.f; }

    // body: one source j = i + q (never j==i since q in [1,127])
    auto body = [&](int q) {
        const int j = i + q;
        float4 pj  = sh_pq[j];
        float4 muj = sh_mu[j];
        const float qj = pj.w;

        float Rx = me.x - pj.x, Ry = me.y - pj.y, Rz = me.z - pj.z;
        float r2 = fmaf(Rx, Rx, fmaf(Ry, Ry, Rz*Rz));
        float inv_r = rsqrtf(r2);
        float r     = r2 * inv_r;
        float hx = Rx * inv_r, hy = Ry * inv_r, hz = Rz * inv_r;
        float muR = fmaf(muj.x, hx, fmaf(muj.y, hy, muj.z * hz));

        float ir2   = inv_r * inv_r;
        float alpha = muR * inv_r;                   // muR/r
        float gamma = inv_r * fmaf(3.0f, alpha, qj); // qj/r + 3 muR/r^2
        float emx = ir2 * muj.x, emy = ir2 * muj.y, emz = ir2 * muj.z;

        #pragma unroll
        for (int t = 0; t < SPT; t++) {
            float e    = ex2_approx(r2 * c2[t]);     // exp(-u^2)
            float d    = fmaf(phw[t], r, 1.0f);      // erf A&S 7.1.26
            float tt   = rcp_approx(d);
            float P    = fmaf(1.061405429f, tt, -1.453152027f);
            P = fmaf(P, tt, 1.421413741f);
            P = fmaf(P, tt, -0.284496736f);
            P = fmaf(P, tt, 0.254829592f);
            float pe   = (P * tt) * e;
            float T    = fmaf(-pe, inv_r, inv_r);    // erf(u)/r
            float D    = fmaf(e, ginv[t], -T);       // gg - T, gg folded
            float A    = fmaf(D, gamma, e * (muR * giw[t]));  // gg*muR*iw2 = e*muR*giw

            // l0 contribution is exactly qj*T - alpha*D
            acc0[t] = fmaf(T, qj, acc0[t]);
            acc0[t] = fmaf(-D, alpha, acc0[t]);
            a1x[t]  = fmaf(A, hx, fmaf(-D, emx, a1x[t]));
            a1y[t]  = fmaf(A, hy, fmaf(-D, emy, a1y[t]));
            a1z[t]  = fmaf(A, hz, fmaf(-D, emz, a1z[t]));
        }
    };

    // slice s covers q = 1+s, 9+s, ... ; slices 0..6 do 16 iters, slice 7 does 15
    #pragma unroll 5
    for (int it = 0; it < 15; it++)
        body(1 + s + 8 * it);
    if (s < 7)
        body(121 + s);

    // stash per-slice partials: red[s][il][v], v = t*4 + c (c: 0=l0,1=x,2=y,3=z)
    #pragma unroll
    for (int t = 0; t < SPT; t++) {
        red[s][il][t*4 + 0] = acc0[t];
        red[s][il][t*4 + 1] = a1x[t];
        red[s][il][t*4 + 2] = a1y[t];
        red[s][il][t*4 + 3] = a1z[t];
    }
    __syncthreads();

    // reduce: thread (il, vv) handles values vv and vv+8 for its receiver
    {
        const int vv   = tid >> 5;          // 0..7 (uniform per warp)
        const int node = g * MN + i;
        float* frow = out + (size_t)node * 64;
        float* srow = out + (size_t)NNODES * 64 + (size_t)node * 64;
        const float qi  = sh_pq[i].w;
        const float4 mui = sh_mu[i];        // (sf3, sf1, sf2) = (x,y,z)

        #pragma unroll
        for (int h = 0; h < 2; h++) {
            const int v = vv + 8 * h;
            const int t = v >> 2;
            const int c = v & 3;
            const int k = sc * SPT + t;
            float sum = 0.f;
            #pragma unroll
            for (int ss = 0; ss < NSL; ss++) sum += red[ss][il][v];

            if (c == 0) {
                frow[k] = rc.l0f[k] * sum;
                srow[k] = rc.si0[k] * qi;
            } else {
                // feature perm: x->+2, y->+0, z->+1 ; si mirrors the same perm
                const int off = (c == 1) ? 2 : (c == 2) ? 0 : 1;
                const float mc = (c == 1) ? mui.x : (c == 2) ? mui.y : mui.z;
                frow[16 + 3*k + off] = rc.l1w[k] * sum;
                srow[16 + 3*k + off] = rc.si1[k] * mc;
            }
        }
    }
}

static RadConsts make_consts() {
    RadConsts rc;
    const double PI  = 3.14159265358979323846;
    const double KCd = 14.399645351950548;
    const double ISQPI = 0.5641895835477562869480794515607725858;
    const double LOG2E = 1.4426950408889634073599246810018921;
    for (int k = 0; k < NRAD; k++) {
        double sig = 0.5 + (double)k * (2.5 / 15.0);
        double w   = sqrt((1.0 + sig*sig) * 0.5);
        double pi15 = pow(PI, 1.5);
        double s3 = sig*sig*sig;
        double s5 = s3*sig*sig;
        double cl0rec  = 1.0 / sqrt(pi15 * s3);
        double cl0mult = 1.0 / (pow(2.0*PI, 1.5) * s3);
        double cl1rec  = 1.0 / sqrt(pi15 * s5 * 3.0 / 2.0);
        double L0F = cl0rec / cl0mult;
        double L1W = sqrt(3.0) * sig * sig * cl1rec / cl0mult;
        double hw = 0.5 / w;
        double gi = ISQPI / w;
        double iw2 = 1.0 / (2.0 * w * w);
        rc.phw[k]        = (float)(0.3275911 * hw);
        rc.negl2e_hw2[k] = (float)(-LOG2E * hw * hw);
        rc.ginv[k]       = (float)gi;
        rc.giw[k]        = (float)(gi * iw2);
        rc.l0f[k]        = (float)(KCd * L0F);
        rc.l1w[k]        = (float)(KCd * L1W);
        rc.si0[k]        = (float)(KCd * L0F * ISQPI / w);
        rc.si1[k]        = (float)(KCd * L1W / (6.0 * w * w * w) * ISQPI);
    }
    return rc;
}

extern "C" void kernel_launch(void* const* d_in, const int* in_sizes, int n_in,
                              void* d_out, int out_size)
{
    const float* sf  = (const float*)d_in[0];  // source_feats (N,4)
    const float* pos = (const float*)d_in[1];  // node_positions (N,3)
    float* out = (float*)d_out;

    static const RadConsts rc = make_consts();  // host-side, FP64, once

    dim3 grid(GRP, SCHUNKS, RSPLIT);
    rsaef_kernel<<<grid, 256>>>(sf, pos, out, rc);
}